// round 2
// baseline (speedup 1.0000x reference)
#include <cuda_runtime.h>
#include <math.h>

// Problem dims
#define BB 1024
#define DD 128
#define WWID 512
#define TT 8
#define NELEM (BB*DD)      // 131072
#define HELEM (BB*WWID)    // 524288
#define MAX_STEPS 48

#define NBLK 128
#define NTHR 256
#define BM 64
#define BN 64
#define BKK 16

// Solver constants
#define RTOLc 1e-3f
#define ATOLc 1e-6f

// Tsit5 tableau
#define A21f 0.161f
#define A31f (-0.008480655492356989f)
#define A32f 0.335480655492357f
#define A41f 2.8971530571054935f
#define A42f (-6.359448489975075f)
#define A43f 4.3622954328695815f
#define A51f 5.325864828439257f
#define A52f (-11.748883564062828f)
#define A53f 7.4955393428898365f
#define A54f (-0.09249506636175525f)
#define A61f 5.86145544294642f
#define A62f (-12.92096931784711f)
#define A63f 8.159367898576159f
#define A64f (-0.071584973281401f)
#define A65f (-0.028269050394068383f)
#define Bc1 0.09646076681806523f
#define Bc2 0.01f
#define Bc3 0.4798896504144996f
#define Bc4 1.379008574103742f
#define Bc5 (-3.290069515436081f)
#define Bc6 2.324710524099774f
#define Ec1 (-0.00178001105222577714f)
#define Ec2 (-0.0008164344596567469f)
#define Ec3 0.007880878010261995f
#define Ec4 (-0.1447110071732629f)
#define Ec5 0.5823571654525552f
#define Ec6 (-0.45808210592918697f)
#define Ec7 0.015151515151515152f

// ---------------- device state ----------------
__device__ __align__(16) float g_y[NELEM];
__device__ __align__(16) float g_ynew[NELEM];
__device__ __align__(16) float g_k[7][NELEM];
__device__ __align__(16) float g_H1[HELEM];
__device__ __align__(16) float g_H2[HELEM];
__device__ __align__(16) float g_part[4][NELEM];
__device__ double g_errpart[NBLK];
__device__ volatile float g_t, g_dt, g_h, g_tns;
__device__ volatile int g_si, g_sic, g_done, g_accept, g_hit, g_wrow;
__device__ unsigned g_arrive;

__constant__ float c_coef[5][5] = {
  {A21f, 0.f,   0.f,   0.f,   0.f},
  {A31f, A32f,  0.f,   0.f,   0.f},
  {A41f, A42f,  A43f,  0.f,   0.f},
  {A51f, A52f,  A53f,  A54f,  0.f},
  {A61f, A62f,  A63f,  A64f,  A65f},
};

// -------- grid-wide barrier (all NBLK CTAs co-resident) --------
__device__ __forceinline__ void gsync() {
  __syncthreads();
  if (threadIdx.x == 0) {
    __threadfence();
    unsigned t = atomicAdd(&g_arrive, 1u) + 1u;
    unsigned target = ((t + NBLK - 1u) / NBLK) * NBLK;
    while (*(volatile unsigned*)&g_arrive < target) {}
    __threadfence();
  }
  __syncthreads();
}

__device__ __forceinline__ float softplus_f(float x) {
  return fmaxf(x, 0.f) + log1pf(expf(-fabsf(x)));
}

// A-source loader. ASRC: 0 -> y, 1..5 -> y + h*sum(a_ij k_j), 6 -> y_new, 7 -> H1, 8 -> H2
template<int ASRC>
__device__ __forceinline__ float4 load_a4(int g, float h) {
  if constexpr (ASRC == 7)      return __ldcg(reinterpret_cast<const float4*>(g_H1 + g));
  else if constexpr (ASRC == 8) return __ldcg(reinterpret_cast<const float4*>(g_H2 + g));
  else if constexpr (ASRC == 0) return __ldcg(reinterpret_cast<const float4*>(g_y + g));
  else if constexpr (ASRC == 6) return __ldcg(reinterpret_cast<const float4*>(g_ynew + g));
  else {
    float4 y4 = __ldcg(reinterpret_cast<const float4*>(g_y + g));
    float sx = 0.f, sy = 0.f, sz = 0.f, sw = 0.f;
    #pragma unroll
    for (int j = 0; j < ASRC; ++j) {
      float c = c_coef[ASRC - 1][j];
      float4 k4 = __ldcg(reinterpret_cast<const float4*>(g_k[j] + g));
      sx = fmaf(c, k4.x, sx); sy = fmaf(c, k4.y, sy);
      sz = fmaf(c, k4.z, sz); sw = fmaf(c, k4.w, sw);
    }
    float4 r;
    r.x = fmaf(h, sx, y4.x); r.y = fmaf(h, sy, y4.y);
    r.z = fmaf(h, sz, y4.z); r.w = fmaf(h, sw, y4.w);
    return r;
  }
}

// ---------- one 64x64 tile of C = act(A[M,K] @ Bw[N,K]^T + bias) ----------
template<int ASRC, int LDA, int NN, int KLEN, bool SP, bool BIAS>
__device__ __forceinline__ void gemm_tile(
    int bm, int bn, int kbase,
    const float* __restrict__ Bw, const float* __restrict__ bias, float h,
    float* __restrict__ C,
    float As[BKK][BM + 4], float Bs[BKK][BN + 4])
{
  const int tid = threadIdx.x;
  const int tx = tid & 15;
  const int ty = tid >> 4;
  const int lrow = tid >> 2;
  const int lkg  = (tid & 3) << 2;

  float acc[4][4] = {};

  // prefetch first tile
  float4 ra = load_a4<ASRC>((bm + lrow) * LDA + kbase + lkg, h);
  float4 rb = __ldg(reinterpret_cast<const float4*>(Bw + (bn + lrow) * LDA + kbase + lkg));

  for (int k0 = 0; k0 < KLEN; k0 += BKK) {
    As[lkg + 0][lrow] = ra.x; As[lkg + 1][lrow] = ra.y;
    As[lkg + 2][lrow] = ra.z; As[lkg + 3][lrow] = ra.w;
    Bs[lkg + 0][lrow] = rb.x; Bs[lkg + 1][lrow] = rb.y;
    Bs[lkg + 2][lrow] = rb.z; Bs[lkg + 3][lrow] = rb.w;
    __syncthreads();
    if (k0 + BKK < KLEN) {
      int gk = kbase + k0 + BKK + lkg;
      ra = load_a4<ASRC>((bm + lrow) * LDA + gk, h);
      rb = __ldg(reinterpret_cast<const float4*>(Bw + (bn + lrow) * LDA + gk));
    }
    #pragma unroll
    for (int kk = 0; kk < BKK; ++kk) {
      float4 a4 = *reinterpret_cast<const float4*>(&As[kk][ty << 2]);
      float4 b4 = *reinterpret_cast<const float4*>(&Bs[kk][tx << 2]);
      float av[4] = {a4.x, a4.y, a4.z, a4.w};
      float bv[4] = {b4.x, b4.y, b4.z, b4.w};
      #pragma unroll
      for (int i = 0; i < 4; ++i)
        #pragma unroll
        for (int j = 0; j < 4; ++j)
          acc[i][j] = fmaf(av[i], bv[j], acc[i][j]);
    }
    __syncthreads();
  }

  #pragma unroll
  for (int i = 0; i < 4; ++i) {
    int m = bm + (ty << 2) + i;
    float4 v; float* vp = &v.x;
    #pragma unroll
    for (int j = 0; j < 4; ++j) {
      float x = acc[i][j];
      if constexpr (BIAS) x += __ldg(bias + bn + (tx << 2) + j);
      if constexpr (SP) x = softplus_f(x);
      vp[j] = x;
    }
    __stcg(reinterpret_cast<float4*>(&C[m * NN + bn + (tx << 2)]), v);
  }
}

// ---------- split-K reduce + fused epilogues ----------
template<int STAGE>
__device__ __forceinline__ void reduce_phase(int bid, int tid,
                                             const float* __restrict__ b2,
                                             double* sd)
{
  const int idx = (bid * NTHR + tid) * 4;
  float4 p0 = __ldcg(reinterpret_cast<const float4*>(g_part[0] + idx));
  float4 p1 = __ldcg(reinterpret_cast<const float4*>(g_part[1] + idx));
  float4 p2 = __ldcg(reinterpret_cast<const float4*>(g_part[2] + idx));
  float4 p3 = __ldcg(reinterpret_cast<const float4*>(g_part[3] + idx));
  float4 bb = *reinterpret_cast<const float4*>(b2 + (idx & (DD - 1)));
  float4 v;
  v.x = p0.x + p1.x + p2.x + p3.x + bb.x;
  v.y = p0.y + p1.y + p2.y + p3.y + bb.y;
  v.z = p0.z + p1.z + p2.z + p3.z + bb.z;
  v.w = p0.w + p1.w + p2.w + p3.w + bb.w;
  __stcg(reinterpret_cast<float4*>(g_k[STAGE] + idx), v);

  if constexpr (STAGE == 5) {
    float h = g_h;
    float4 k0 = __ldcg(reinterpret_cast<const float4*>(g_k[0] + idx));
    float4 k1 = __ldcg(reinterpret_cast<const float4*>(g_k[1] + idx));
    float4 k2 = __ldcg(reinterpret_cast<const float4*>(g_k[2] + idx));
    float4 k3 = __ldcg(reinterpret_cast<const float4*>(g_k[3] + idx));
    float4 k4 = __ldcg(reinterpret_cast<const float4*>(g_k[4] + idx));
    float4 y4 = __ldcg(reinterpret_cast<const float4*>(g_y + idx));
    float4 yn;
    #pragma unroll
    for (int c = 0; c < 4; ++c) {
      float s = Bc1 * (&k0.x)[c];
      s = fmaf(Bc2, (&k1.x)[c], s);
      s = fmaf(Bc3, (&k2.x)[c], s);
      s = fmaf(Bc4, (&k3.x)[c], s);
      s = fmaf(Bc5, (&k4.x)[c], s);
      s = fmaf(Bc6, (&v.x)[c], s);
      (&yn.x)[c] = fmaf(h, s, (&y4.x)[c]);
    }
    __stcg(reinterpret_cast<float4*>(g_ynew + idx), yn);
  }

  if constexpr (STAGE == 6) {
    float h = g_h;
    float4 k0 = __ldcg(reinterpret_cast<const float4*>(g_k[0] + idx));
    float4 k1 = __ldcg(reinterpret_cast<const float4*>(g_k[1] + idx));
    float4 k2 = __ldcg(reinterpret_cast<const float4*>(g_k[2] + idx));
    float4 k3 = __ldcg(reinterpret_cast<const float4*>(g_k[3] + idx));
    float4 k4 = __ldcg(reinterpret_cast<const float4*>(g_k[4] + idx));
    float4 k5 = __ldcg(reinterpret_cast<const float4*>(g_k[5] + idx));
    float4 y4 = __ldcg(reinterpret_cast<const float4*>(g_y + idx));
    float4 yn = __ldcg(reinterpret_cast<const float4*>(g_ynew + idx));
    double ss = 0.0;
    #pragma unroll
    for (int c = 0; c < 4; ++c) {
      float e = Ec1 * (&k0.x)[c];
      e = fmaf(Ec2, (&k1.x)[c], e);
      e = fmaf(Ec3, (&k2.x)[c], e);
      e = fmaf(Ec4, (&k3.x)[c], e);
      e = fmaf(Ec5, (&k4.x)[c], e);
      e = fmaf(Ec6, (&k5.x)[c], e);
      e = fmaf(Ec7, (&v.x)[c], e);
      float err = h * e;
      float scale = ATOLc + RTOLc * fmaxf(fabsf((&y4.x)[c]), fabsf((&yn.x)[c]));
      float r = err / scale;
      ss += (double)r * (double)r;
    }
    sd[tid] = ss;
    __syncthreads();
    #pragma unroll
    for (int s2 = 128; s2 > 0; s2 >>= 1) {
      if (tid < s2) sd[tid] += sd[tid + s2];
      __syncthreads();
    }
    if (tid == 0) ((volatile double*)g_errpart)[bid] = sd[0];
  }
}

// ---------- one RK stage ----------
template<int S>
__device__ __forceinline__ void do_stage(
    int bid,
    const float* __restrict__ W0, const float* __restrict__ b0,
    const float* __restrict__ W1, const float* __restrict__ b1,
    const float* __restrict__ W2, const float* __restrict__ b2,
    float As[BKK][BM + 4], float Bs[BKK][BN + 4], double* sd)
{
  const float h = g_h;
  {
    int bm = (bid >> 3) << 6, bn = (bid & 7) << 6;
    gemm_tile<S, 128, 512, 128, true, true>(bm, bn, 0, W0, b0, h, g_H1, As, Bs);
  }
  gsync();
  {
    int bm = (bid >> 3) << 6, bn = (bid & 7) << 6;
    gemm_tile<7, 512, 512, 512, true, true>(bm, bn, 0, W1, b1, h, g_H2, As, Bs);
  }
  gsync();
  {
    int slice = bid & 3, tile = bid >> 2;
    int bm = (tile >> 1) << 6, bn = (tile & 1) << 6;
    gemm_tile<8, 512, 128, 128, false, false>(bm, bn, slice * 128, W2, nullptr, h,
                                              g_part[slice], As, Bs);
  }
  gsync();
  reduce_phase<S>(bid, threadIdx.x, b2, sd);
  gsync();
}

__device__ __forceinline__ void update_phase(int gid4, float* __restrict__ out) {
  if (g_accept) {
    float4 v = __ldcg(reinterpret_cast<const float4*>(g_ynew + gid4));
    __stcg(reinterpret_cast<float4*>(g_y + gid4), v);
    if (g_hit) {
      int r = g_wrow;
      *reinterpret_cast<float4*>(out + r * NELEM + gid4) = v;
    }
  }
}

// ---------- persistent solver ----------
__global__ void __launch_bounds__(NTHR, 1) solve_kernel(
    const float* __restrict__ ts,
    const float* __restrict__ W0, const float* __restrict__ b0,
    const float* __restrict__ W1, const float* __restrict__ b1,
    const float* __restrict__ W2, const float* __restrict__ b2,
    float* __restrict__ out)
{
  __shared__ float As[BKK][BM + 4];
  __shared__ float Bs[BKK][BN + 4];
  __shared__ double sd[NTHR];

  const int bid = blockIdx.x;
  const int tid = threadIdx.x;
  const int gid4 = (bid * NTHR + tid) * 4;

  for (int step = 0; step < MAX_STEPS; ++step) {
    // phase P: apply previous step's update + compute this step's h (block 0)
    update_phase(gid4, out);
    if (bid == 0 && tid == 0) {
      int si = g_si;
      int done = (si >= TT) ? 1 : 0;
      int sic = si < (TT - 1) ? si : (TT - 1);
      float tns = __ldg(ts + sic);
      float h = done ? 0.f : fmaxf(fminf(g_dt, tns - g_t), 0.f);
      g_done = done; g_sic = sic; g_tns = tns; g_h = h;
    }
    gsync();

    do_stage<0>(bid, W0, b0, W1, b1, W2, b2, As, Bs, sd);
    do_stage<1>(bid, W0, b0, W1, b1, W2, b2, As, Bs, sd);
    do_stage<2>(bid, W0, b0, W1, b1, W2, b2, As, Bs, sd);
    do_stage<3>(bid, W0, b0, W1, b1, W2, b2, As, Bs, sd);
    do_stage<4>(bid, W0, b0, W1, b1, W2, b2, As, Bs, sd);
    do_stage<5>(bid, W0, b0, W1, b1, W2, b2, As, Bs, sd);
    do_stage<6>(bid, W0, b0, W1, b1, W2, b2, As, Bs, sd);

    // control post (block 0 reduces error partials, updates controller state)
    if (bid == 0) {
      double v = (tid < NBLK) ? ((volatile double*)g_errpart)[tid] : 0.0;
      sd[tid] = v;
      __syncthreads();
      #pragma unroll
      for (int s2 = 128; s2 > 0; s2 >>= 1) {
        if (tid < s2) sd[tid] += sd[tid + s2];
        __syncthreads();
      }
      if (tid == 0) {
        float enorm = sqrtf((float)(sd[0] / (double)NELEM));
        int done = g_done;
        float h = g_h;
        int accept = (enorm <= 1.0f) && !done;
        float t_new = g_t + h;
        int hit = accept && (t_new >= g_tns - 1e-6f);
        if (accept) g_t = t_new;
        g_accept = accept;
        g_hit = hit;
        g_wrow = g_sic;
        g_si = g_si + hit;
        float factor;
        if (enorm > 0.f) {
          factor = 0.9f * powf(enorm, -0.2f);
          factor = fminf(fmaxf(factor, 0.2f), 10.f);
        } else {
          factor = 10.f;
        }
        if (!done) g_dt = g_dt * factor;
      }
    }
    gsync();
  }
  // final update for the last step
  update_phase(gid4, out);
}

__global__ void init_kernel(const float* __restrict__ ts,
                            const float* __restrict__ y0,
                            float* __restrict__ out) {
  int idx = blockIdx.x * NTHR + threadIdx.x;   // grid covers TT*NELEM
  if (idx < NELEM) {
    float v = y0[idx];
    out[idx] = v;
    g_y[idx] = v;
  } else {
    out[idx] = 0.f;
  }
  if (idx == 0) {
    g_t = ts[0];
    g_dt = ts[1] - ts[0];
    g_si = 1;
    g_accept = 0;
    g_hit = 0;
    g_wrow = 0;
    g_arrive = 0u;
  }
}

extern "C" void kernel_launch(void* const* d_in, const int* in_sizes, int n_in,
                              void* d_out, int out_size) {
  const float* ts = (const float*)d_in[0];
  const float* y0 = (const float*)d_in[1];
  const float* W0 = (const float*)d_in[2];
  const float* b0 = (const float*)d_in[3];
  const float* W1 = (const float*)d_in[4];
  const float* b1 = (const float*)d_in[5];
  const float* W2 = (const float*)d_in[6];
  const float* b2 = (const float*)d_in[7];
  float* out = (float*)d_out;

  init_kernel<<<(TT * NELEM) / NTHR, NTHR>>>(ts, y0, out);
  solve_kernel<<<NBLK, NTHR>>>(ts, W0, b0, W1, b1, W2, b2, out);
}